// round 16
// baseline (speedup 1.0000x reference)
#include <cuda_runtime.h>
#include <cuda_bf16.h>
#include <cstdint>

#define B_    256
#define NA_   196
#define NB_   196
#define DK_   256
#define DIM_  1024
#define SMOOTH_ 4.0f

typedef unsigned long long ull;

// ---------------- scratch ----------------
// attn stored as tf32-rounded fp32 bit patterns (consumed raw by mma.tf32).
__device__ float g_attn[(size_t)B_ * NA_ * NB_];
// chunk-blocked bf16 hi/lo copies: [b][c(=k/32)][row(224)][kk(32)]
__device__ __nv_bfloat16 g_qh[(size_t)B_ * 8 * 224 * 32];
__device__ __nv_bfloat16 g_ql[(size_t)B_ * 8 * 224 * 32];
__device__ __nv_bfloat16 g_kh[(size_t)B_ * 8 * 224 * 32];
__device__ __nv_bfloat16 g_kl[(size_t)B_ * 8 * 224 * 32];

// ---------------- PTX helpers (plain sm_80+ PTX only) ----------------
__device__ __forceinline__ uint32_t f2tf32(float x) {
    uint32_t u;
    asm("cvt.rna.tf32.f32 %0, %1;" : "=r"(u) : "f"(x));
    return u;
}
__device__ __forceinline__ uint32_t smem_u32(const void* p) {
    uint32_t a;
    asm("{ .reg .u64 t; cvta.to.shared.u64 t, %1; cvt.u32.u64 %0, t; }"
        : "=r"(a) : "l"(p));
    return a;
}

#define CP_ASYNC16(dst, src, sz)                                              \
    asm volatile("cp.async.cg.shared.global [%0], [%1], 16, %2;"              \
        :: "r"(dst), "l"(src), "r"(sz) : "memory")
#define CP_COMMIT()  asm volatile("cp.async.commit_group;" ::: "memory")
#define CP_WAIT1()   asm volatile("cp.async.wait_group 1;" ::: "memory")
#define CP_WAIT0()   asm volatile("cp.async.wait_group 0;" ::: "memory")

#define MMA_TF32(c, a, b)                                                     \
    asm volatile(                                                             \
        "mma.sync.aligned.m16n8k8.row.col.f32.tf32.tf32.f32 "                 \
        "{%0,%1,%2,%3}, {%4,%5,%6,%7}, {%8,%9}, {%0,%1,%2,%3};"               \
        : "+f"((c)[0]), "+f"((c)[1]), "+f"((c)[2]), "+f"((c)[3])              \
        : "r"((a)[0]), "r"((a)[1]), "r"((a)[2]), "r"((a)[3]),                 \
          "r"((b)[0]), "r"((b)[1]))

#define MMA_BF16(c, a, b)                                                     \
    asm volatile(                                                             \
        "mma.sync.aligned.m16n8k16.row.col.f32.bf16.bf16.f32 "                \
        "{%0,%1,%2,%3}, {%4,%5,%6,%7}, {%8,%9}, {%0,%1,%2,%3};"               \
        : "+f"((c)[0]), "+f"((c)[1]), "+f"((c)[2]), "+f"((c)[3])              \
        : "r"((a)[0]), "r"((a)[1]), "r"((a)[2]), "r"((a)[3]),                 \
          "r"((b)[0]), "r"((b)[1]))

__device__ __forceinline__ void bf16_split(float v, __nv_bfloat16& h,
                                           __nv_bfloat16& l) {
    h = __float2bfloat16_rn(v);
    l = __float2bfloat16_rn(v - __bfloat162float(h));
}

// ---------------------------------------------------------------------------
// convQ: Q[b][a][k] fp32 -> g_qh/g_ql[b][c][a][kk] bf16 (a padded to 224).
// ---------------------------------------------------------------------------
__global__ __launch_bounds__(256) void convq_kernel(const float* __restrict__ q)
{
    const int c = blockIdx.x, b = blockIdx.y;
    const size_t obase = ((size_t)(b * 8 + c)) * 224 * 32;
    const float* __restrict__ qb = q + (size_t)b * NA_ * DK_ + c * 32;

    for (int i = threadIdx.x; i < 224 * 32; i += 256) {
        const int a = i >> 5, kk = i & 31;
        float v = 0.f;
        if (a < NA_) v = qb[(size_t)a * DK_ + kk];
        __nv_bfloat16 h, l;
        bf16_split(v, h, l);
        g_qh[obase + i] = h;
        g_ql[obase + i] = l;
    }
}

// ---------------------------------------------------------------------------
// convK: K[b][k][n] fp32 -> transposed g_kh/g_kl[b][c][n][kk] bf16.
// ---------------------------------------------------------------------------
__global__ __launch_bounds__(256) void convk_kernel(const float* __restrict__ kb)
{
    __shared__ float T[32 * 225];
    const int c = blockIdx.x, b = blockIdx.y;
    const size_t obase = ((size_t)(b * 8 + c)) * 224 * 32;
    const float* __restrict__ kbb = kb + ((size_t)b * DK_ + c * 32) * NB_;

    for (int i = threadIdx.x; i < 32 * 224; i += 256) {
        const int kk = i / 224, n = i - kk * 224;
        T[kk * 225 + n] = (n < NB_) ? kbb[(size_t)kk * NB_ + n] : 0.f;
    }
    __syncthreads();
    for (int i = threadIdx.x; i < 224 * 32; i += 256) {
        const int n = i >> 5, kk = i & 31;
        __nv_bfloat16 h, l;
        bf16_split(T[kk * 225 + n], h, l);
        g_kh[obase + i] = h;
        g_kl[obase + i] = l;
    }
}

// ---------------------------------------------------------------------------
// energy+softmax (bf16-split HMMA) — unchanged; attn stored as tf32 bits.
// ---------------------------------------------------------------------------
#define EP 20

__global__ __launch_bounds__(128, 4) void energy_mma_kernel()
{
    __shared__ uint32_t SM[10240];
    uint32_t* Kh = SM;
    uint32_t* Kl = SM + 4480;
    uint32_t* Qh = SM + 8960;
    uint32_t* Ql = SM + 9600;
    float*    Es = (float*)SM;

    const int b    = blockIdx.y;
    const int a0   = blockIdx.x * 32;
    const int tid  = threadIdx.x;
    const int wid  = tid >> 5;
    const int lane = tid & 31;
    const int grp  = lane >> 2;
    const int tg   = lane & 3;
    const int wc   = wid * 56;

    float acc[2][7][4];
#pragma unroll
    for (int i = 0; i < 2; i++)
#pragma unroll
        for (int j = 0; j < 7; j++)
#pragma unroll
            for (int e = 0; e < 4; e++) acc[i][j][e] = 0.f;

    for (int c = 0; c < 8; c++) {
        const size_t kb0 = ((size_t)(b * 8 + c)) * 224 * 32;
        const size_t qb0 = kb0 + (size_t)a0 * 32;
        const uint4* __restrict__ skh = (const uint4*)(g_kh + kb0);
        const uint4* __restrict__ skl = (const uint4*)(g_kl + kb0);
        const uint4* __restrict__ sqh = (const uint4*)(g_qh + qb0);
        const uint4* __restrict__ sql = (const uint4*)(g_ql + qb0);

#pragma unroll
        for (int s = 0; s < 7; s++) {
            const int u = tid + s * 128;
            const int n = u >> 2, qq = u & 3;
            *(uint4*)&Kh[n * EP + 4 * qq] = skh[u];
            *(uint4*)&Kl[n * EP + 4 * qq] = skl[u];
        }
        {
            const int a = tid >> 2, qq = tid & 3;
            *(uint4*)&Qh[a * EP + 4 * qq] = sqh[tid];
            *(uint4*)&Ql[a * EP + 4 * qq] = sql[tid];
        }
        __syncthreads();

#pragma unroll
        for (int s = 0; s < 2; s++) {
            const int w0 = s * 8 + tg;
            uint32_t ah[2][4], al[2][4];
#pragma unroll
            for (int i = 0; i < 2; i++) {
                const int r = i * 16 + grp;
                ah[i][0] = Qh[r * EP + w0];       al[i][0] = Ql[r * EP + w0];
                ah[i][1] = Qh[(r + 8) * EP + w0]; al[i][1] = Ql[(r + 8) * EP + w0];
                ah[i][2] = Qh[r * EP + w0 + 4];   al[i][2] = Ql[r * EP + w0 + 4];
                ah[i][3] = Qh[(r + 8) * EP + w0 + 4];
                al[i][3] = Ql[(r + 8) * EP + w0 + 4];
            }
            uint32_t bh[7][2], bl[7][2];
#pragma unroll
            for (int j = 0; j < 7; j++) {
                const int col = wc + j * 8 + grp;
                bh[j][0] = Kh[col * EP + w0];     bl[j][0] = Kl[col * EP + w0];
                bh[j][1] = Kh[col * EP + w0 + 4]; bl[j][1] = Kl[col * EP + w0 + 4];
            }
#pragma unroll
            for (int i = 0; i < 2; i++)
#pragma unroll
                for (int j = 0; j < 7; j++) {
                    MMA_BF16(acc[i][j], ah[i], bh[j]);
                    MMA_BF16(acc[i][j], ah[i], bl[j]);
                    MMA_BF16(acc[i][j], al[i], bh[j]);
                }
        }
        __syncthreads();
    }

#pragma unroll
    for (int i = 0; i < 2; i++) {
#pragma unroll
        for (int j = 0; j < 7; j++) {
            const int col = wc + j * 8 + 2 * tg;
            const int r0 = i * 16 + grp;
            *(float2*)&Es[r0 * 228 + col] =
                make_float2(acc[i][j][0], acc[i][j][1]);
            *(float2*)&Es[(r0 + 8) * 228 + col] =
                make_float2(acc[i][j][2], acc[i][j][3]);
        }
    }
    __syncthreads();

    float* __restrict__ attb = g_attn + (size_t)b * NA_ * NB_;
#pragma unroll
    for (int rr = 0; rr < 8; rr++) {
        const int row = wid * 8 + rr;
        const int a = a0 + row;
        if (a >= NA_) break;
        float v[7];
        float m = -1e30f;
#pragma unroll
        for (int t = 0; t < 7; t++) {
            const int n = lane + 32 * t;
            v[t] = (n < NB_) ? Es[row * 228 + n] : -1e30f;
            m = fmaxf(m, v[t]);
        }
#pragma unroll
        for (int off = 16; off > 0; off >>= 1)
            m = fmaxf(m, __shfl_xor_sync(0xffffffffu, m, off));
        float s = 0.f;
#pragma unroll
        for (int t = 0; t < 7; t++) {
            v[t] = __expf(SMOOTH_ * (v[t] - m));
            s += v[t];
        }
#pragma unroll
        for (int off = 16; off > 0; off >>= 1)
            s += __shfl_xor_sync(0xffffffffu, s, off);
        const float inv = 1.0f / s;
#pragma unroll
        for (int t = 0; t < 7; t++) {
            const int n = lane + 32 * t;
            if (n < NB_)
                attb[(size_t)a * NB_ + n] =
                    __uint_as_float(f2tf32(v[t] * inv));
        }
    }
}

// ---------------------------------------------------------------------------
// Kernel 3 (mma.sync tf32, cp.async double-buffered): out = V@attn + vb + g.
// M=128(d) x N=112(n) per CTA, 256 thr = 8 warps (4m x 2n), warp tile 32x56.
// Halves attn L2 traffic vs M=64 (8 d-blocks re-read attn instead of 16) and
// amortizes each As fill over 2x the MMAs. Buffers: Vs[128*36]+As[32*120] =
// 8448 words; 2 buffers = 66 KB dyn smem -> 2 CTAs/SM (16 warps, same as
// before). attn pre-tf32, V raw fp32 bits (HW truncation).
// ---------------------------------------------------------------------------
#define OB_WORDS 8448
#define OUT_SMEM_BYTES (2 * OB_WORDS * 4)

__global__ __launch_bounds__(256, 2) void out_mma_kernel(
    const float* __restrict__ va, const float* __restrict__ vbb,
    const float* __restrict__ gamma, float* __restrict__ out)
{
    extern __shared__ uint32_t DYN[];
    const uint32_t sbase = smem_u32(DYN);

    const int b   = blockIdx.z;
    const int d0  = blockIdx.x * 128;
    const int n0  = blockIdx.y * 112;
    const int tid = threadIdx.x;
    const int wid = tid >> 5;
    const int lane = tid & 31;
    const int grp = lane >> 2;
    const int tg  = lane & 3;
    const int wm  = wid >> 1;           // 0..3 -> d offset 32*wm
    const int wn  = wid & 1;            // 0..1 -> n offset 56*wn

    const float* __restrict__ vab  = va + ((size_t)b * DIM_ + d0) * NA_;
    const float* __restrict__ attb = g_attn + (size_t)b * NA_ * NB_;

    // per-thread fill coordinates (fixed across chunks)
    const int vd = tid >> 3, vm4 = (tid & 7) * 4;   // Vs: d = vd + s*32

    float acc[2][7][4];
#pragma unroll
    for (int i = 0; i < 2; i++)
#pragma unroll
        for (int j = 0; j < 7; j++)
#pragma unroll
            for (int e = 0; e < 4; e++) acc[i][j][e] = 0.f;

    // ---- async fill of one chunk into buffer p ----
    auto issue = [&](int kc, int p) {
        const uint32_t vbase = sbase + (uint32_t)(p * OB_WORDS) * 4u;
        const uint32_t abase = vbase + 4608u * 4u;
        // Vs: 128 d-rows x 8 uint4 (32 k) = 1024 -> 4/thread
#pragma unroll
        for (int s = 0; s < 4; s++) {
            const int d = vd + s * 32;
            const int kcol = kc + vm4;
            const uint32_t sz = (kcol + 3 < NA_) ? 16u : 0u;
            const float* src = vab + (size_t)d * NA_ + (sz ? kcol : 0);
            CP_ASYNC16(vbase + (uint32_t)(d * 36 + vm4) * 4u, src, sz);
        }
        // As: 32 k-rows x 28 uint4 (112 n) = 896 -> <=4/thread
#pragma unroll
        for (int s = 0; s < 4; s++) {
            const int u = tid + s * 256;
            if (u < 896) {
                const int kk = u / 28, m4 = (u - kk * 28) * 4;
                const int row = kc + kk;
                const uint32_t sz =
                    (row < NA_ && n0 + m4 + 3 < NB_) ? 16u : 0u;
                const float* src =
                    attb + (sz ? ((size_t)row * NB_ + n0 + m4) : 0);
                CP_ASYNC16(abase + (uint32_t)(kk * 120 + m4) * 4u, src, sz);
            }
        }
        CP_COMMIT();
    };

    issue(0, 0);

    for (int c = 0; c < 7; c++) {
        if (c < 6) { issue((c + 1) * 32, (c + 1) & 1); CP_WAIT1(); }
        else       { CP_WAIT0(); }
        __syncthreads();

        const uint32_t* Vs = DYN + (c & 1) * OB_WORDS;
        const uint32_t* As = Vs + 4608;

#pragma unroll
        for (int ks = 0; ks < 4; ks++) {
            const int k0 = ks * 8;
            uint32_t af[2][4];
#pragma unroll
            for (int i = 0; i < 2; i++) {
                const int r = wm * 32 + i * 16 + grp;
                af[i][0] = Vs[r * 36 + k0 + tg];
                af[i][1] = Vs[(r + 8) * 36 + k0 + tg];
                af[i][2] = Vs[r * 36 + k0 + tg + 4];
                af[i][3] = Vs[(r + 8) * 36 + k0 + tg + 4];
            }
            uint32_t bf[7][2];
#pragma unroll
            for (int j = 0; j < 7; j++) {
                const int col = wn * 56 + j * 8 + grp;
                bf[j][0] = As[(k0 + tg) * 120 + col];
                bf[j][1] = As[(k0 + tg + 4) * 120 + col];
            }
#pragma unroll
            for (int i = 0; i < 2; i++)
#pragma unroll
                for (int j = 0; j < 7; j++)
                    MMA_TF32(acc[i][j], af[i], bf[j]);
        }
        __syncthreads();
    }

    const float g0 = gamma[0];
#pragma unroll
    for (int i = 0; i < 2; i++) {
        const int row = d0 + wm * 32 + i * 16 + grp;
#pragma unroll
        for (int j = 0; j < 7; j++) {
            const int col = n0 + wn * 56 + j * 8 + tg * 2;
            if (col < NB_) {
                const size_t o  = ((size_t)b * DIM_ + row) * NB_ + col;
                const size_t o2 = o + (size_t)8 * NB_;
                const float2 w  = *(const float2*)&vbb[o];
                const float2 w2 = *(const float2*)&vbb[o2];
                float2 r, r2;
                r.x  = acc[i][j][0] + w.x  + g0;
                r.y  = acc[i][j][1] + w.y  + g0;
                r2.x = acc[i][j][2] + w2.x + g0;
                r2.y = acc[i][j][3] + w2.y + g0;
                *(float2*)&out[o]  = r;
                *(float2*)&out[o2] = r2;
            }
        }
    }
}

// ---------------------------------------------------------------------------
extern "C" void kernel_launch(void* const* d_in, const int* in_sizes, int n_in,
                              void* d_out, int out_size)
{
    (void)in_sizes; (void)n_in; (void)out_size;
    const float* q     = (const float*)d_in[0];  // [B, Na, Dk]
    const float* va    = (const float*)d_in[1];  // [B, Dim, Na]
    const float* kb    = (const float*)d_in[2];  // [B, Dk, Nb]
    const float* vb    = (const float*)d_in[3];  // [B, Dim, Nb]
    const float* gamma = (const float*)d_in[4];  // [1]
    float* out = (float*)d_out;                  // [B, Dim, Nb]

    convq_kernel<<<dim3(8, B_), 256>>>(q);
    convk_kernel<<<dim3(8, B_), 256>>>(kb);
    energy_mma_kernel<<<dim3(7, B_), 128>>>();

    cudaFuncSetAttribute(out_mma_kernel,
                         cudaFuncAttributeMaxDynamicSharedMemorySize,
                         OUT_SMEM_BYTES);
    out_mma_kernel<<<dim3(8, 2, B_), 256, OUT_SMEM_BYTES>>>(
        va, vb, gamma, out);
}